// round 1
// baseline (speedup 1.0000x reference)
#include <cuda_runtime.h>
#include <math.h>

#define B 8
#define WLEN 1000
#define EMB 100
#define C 50
#define KK 3
#define L 18000

#define BL 64        // labels per block
#define WC 128       // w per chunk
#define NCHUNK 8     // ceil(1000/128)
#define THREADS 256

// H transposed: [b][c][w], fp32 scratch
__device__ float g_H[B * C * WLEN];

// ---------------------------------------------------------------------------
// Kernel 1: embedding lookup + conv1d(same) + tanh, store H transposed [b,c,w]
// ---------------------------------------------------------------------------
__global__ void conv_kernel(const int* __restrict__ x,
                            const float* __restrict__ W_embed,
                            const float* __restrict__ conv_w,
                            const float* __restrict__ conv_b) {
    int idx = blockIdx.x * blockDim.x + threadIdx.x;
    if (idx >= B * WLEN * C) return;
    int c = idx % C;
    int w = (idx / C) % WLEN;
    int b = idx / (C * WLEN);

    float acc = conv_b[c];
#pragma unroll
    for (int k = 0; k < KK; k++) {
        int wi = w + k - 1;
        if (wi < 0 || wi >= WLEN) continue;
        int xv = x[b * WLEN + wi];
        const float* er = W_embed + (long)xv * EMB;
        const float* cw = conv_w + c * EMB * KK + k;
#pragma unroll 4
        for (int e = 0; e < EMB; e++)
            acc = fmaf(er[e], cw[e * KK], acc);
    }
    g_H[(b * C + c) * WLEN + w] = tanhf(acc);
}

// ---------------------------------------------------------------------------
// Kernel 2: fused dual-GEMM (scores + pooled dot) + online softmax + sigmoid
//   out[b,l] = sigmoid( sum_w softmax_w(u_w[l].H[b,w]) * (out_w[l].H[b,w]) + out_b[l] )
// Block: 64 labels x one batch. Thread: 4 labels (ty) x 8 w (tx, split 4+4).
// ---------------------------------------------------------------------------
__global__ __launch_bounds__(THREADS, 2)
void attn_kernel(const float* __restrict__ u_w,
                 const float* __restrict__ out_w,
                 const float* __restrict__ out_b,
                 float* __restrict__ out) {
    __shared__ float u_s[C][BL];   // k-major
    __shared__ float o_s[C][BL];
    __shared__ float Hs[C][WC];    // k-major chunk of H[b]

    const int b   = blockIdx.y;
    const int l0  = blockIdx.x * BL;
    const int tid = threadIdx.x;
    const int tx  = tid & 15;      // w group (16)
    const int ty  = tid >> 4;      // label group (16)

    // Load label weight tiles once (k-major, coalesced smem writes)
    for (int i = tid; i < C * BL; i += THREADS) {
        int li = i % BL;
        int k  = i / BL;
        int l  = l0 + li;
        float uv = 0.f, ov = 0.f;
        if (l < L) { uv = u_w[l * C + k]; ov = out_w[l * C + k]; }
        u_s[k][li] = uv;
        o_s[k][li] = ov;
    }

    float m[4], d[4], n[4];
#pragma unroll
    for (int i = 0; i < 4; i++) { m[i] = -INFINITY; d[i] = 0.f; n[i] = 0.f; }

    for (int ch = 0; ch < NCHUNK; ch++) {
        const int base = ch * WC;
        __syncthreads();
        // Load H chunk as float4 (WLEN=1000 is float4-aligned per row)
        {
            const float4* src = (const float4*)g_H;
            float4* dst = (float4*)Hs;
            int base4 = base >> 2;
            for (int i = tid; i < C * WC / 4; i += THREADS) {
                int k  = i >> 5;        // /32 float4s per row
                int j4 = i & 31;
                int w4 = base4 + j4;
                float4 v = make_float4(0.f, 0.f, 0.f, 0.f);
                if (w4 < WLEN / 4) v = src[(b * C + k) * (WLEN / 4) + w4];
                dst[k * (WC / 4) + j4] = v;
            }
        }
        __syncthreads();

        float s[4][8], p[4][8];
#pragma unroll
        for (int i = 0; i < 4; i++)
#pragma unroll
            for (int j = 0; j < 8; j++) { s[i][j] = 0.f; p[i][j] = 0.f; }

#pragma unroll 2
        for (int k = 0; k < C; k++) {
            float4 u4 = *(const float4*)&u_s[k][ty * 4];
            float4 o4 = *(const float4*)&o_s[k][ty * 4];
            float4 ha = *(const float4*)&Hs[k][tx * 4];
            float4 hb = *(const float4*)&Hs[k][64 + tx * 4];
            float uv[4] = {u4.x, u4.y, u4.z, u4.w};
            float ov[4] = {o4.x, o4.y, o4.z, o4.w};
            float hv[8] = {ha.x, ha.y, ha.z, ha.w, hb.x, hb.y, hb.z, hb.w};
#pragma unroll
            for (int i = 0; i < 4; i++)
#pragma unroll
                for (int j = 0; j < 8; j++) {
                    s[i][j] = fmaf(uv[i], hv[j], s[i][j]);
                    p[i][j] = fmaf(ov[i], hv[j], p[i][j]);
                }
        }

        // Mask invalid w, then per-thread online softmax update
        const int wA = base + tx * 4;        // j = 0..3
        const int wB = base + 64 + tx * 4;   // j = 4..7
#pragma unroll
        for (int i = 0; i < 4; i++) {
#pragma unroll
            for (int j = 0; j < 4; j++) {
                if (wA + j >= WLEN) s[i][j]     = -1e30f;
                if (wB + j >= WLEN) s[i][4 + j] = -1e30f;
            }
            float cm = s[i][0];
#pragma unroll
            for (int j = 1; j < 8; j++) cm = fmaxf(cm, s[i][j]);
            float mn = fmaxf(m[i], cm);
            float sc = __expf(m[i] - mn);     // exp(-inf)=0 handles first chunk
            float dd = d[i] * sc;
            float nn = n[i] * sc;
#pragma unroll
            for (int j = 0; j < 8; j++) {
                float e = __expf(s[i][j] - mn);
                dd += e;
                nn = fmaf(e, p[i][j], nn);
            }
            m[i] = mn; d[i] = dd; n[i] = nn;
        }
    }

    // Merge 16 partial (m,d,n) triples per label across tx lanes (same warp half)
#pragma unroll
    for (int i = 0; i < 4; i++) {
#pragma unroll
        for (int off = 8; off >= 1; off >>= 1) {
            float mo = __shfl_xor_sync(0xffffffff, m[i], off);
            float dd = __shfl_xor_sync(0xffffffff, d[i], off);
            float nn = __shfl_xor_sync(0xffffffff, n[i], off);
            float mn = fmaxf(m[i], mo);
            float sa = __expf(m[i] - mn);
            float sb = __expf(mo   - mn);
            d[i] = d[i] * sa + dd * sb;
            n[i] = n[i] * sa + nn * sb;
            m[i] = mn;
        }
    }

    if (tx == 0) {
#pragma unroll
        for (int i = 0; i < 4; i++) {
            int l = l0 + ty * 4 + i;
            if (l < L) {
                float z = n[i] / d[i] + out_b[l];
                out[b * L + l] = 1.f / (1.f + __expf(-z));
            }
        }
    }
}

// ---------------------------------------------------------------------------
extern "C" void kernel_launch(void* const* d_in, const int* in_sizes, int n_in,
                              void* d_out, int out_size) {
    const int*   x       = (const int*)  d_in[0];
    const float* W_embed = (const float*)d_in[1];
    const float* conv_w  = (const float*)d_in[2];
    const float* conv_b  = (const float*)d_in[3];
    const float* u_w     = (const float*)d_in[4];
    const float* out_w   = (const float*)d_in[5];
    const float* out_b   = (const float*)d_in[6];
    float* out = (float*)d_out;

    int n1 = B * WLEN * C;
    conv_kernel<<<(n1 + 255) / 256, 256>>>(x, W_embed, conv_w, conv_b);

    dim3 grid((L + BL - 1) / BL, B);   // (282, 8)
    attn_kernel<<<grid, THREADS>>>(u_w, out_w, out_b, out);
}

// round 3
// speedup vs baseline: 3.0099x; 3.0099x over previous
#include <cuda_runtime.h>
#include <math.h>
#include <stdint.h>

#define BB   8
#define WLEN 1000
#define EMB  100
#define CC   50
#define LL   18000

// H transposed scratch: [b][c][w] fp32
__device__ float g_H[BB * CC * WLEN];

// ===========================================================================
// Kernel 1: embedding + conv1d(k=3, same) + tanh  -> g_H[b][c][w]
// smem-tiled: each embedding row gathered once per tile
// ===========================================================================
#define CT_W    40
#define CT_ROWS (CT_W + 2)

__global__ __launch_bounds__(256)
void conv_kernel(const int* __restrict__ x, const float* __restrict__ W_embed,
                 const float* __restrict__ conv_w, const float* __restrict__ conv_b) {
    __shared__ float emb_s[CT_ROWS][EMB + 1];
    __shared__ int   tok_s[CT_ROWS];
    const int b  = blockIdx.y;
    const int w0 = blockIdx.x * CT_W;
    const int tid = threadIdx.x;

    if (tid < CT_ROWS) {
        int w = w0 - 1 + tid;
        tok_s[tid] = (w >= 0 && w < WLEN) ? x[b * WLEN + w] : -1;
    }
    __syncthreads();
    for (int i = tid; i < CT_ROWS * EMB; i += 256) {
        int r = i / EMB, e = i - r * EMB;
        int t = tok_s[r];
        emb_s[r][e] = (t >= 0) ? W_embed[(long)t * EMB + e] : 0.f;
    }
    __syncthreads();

    if (tid < 250) {
        int c = tid / 5, q = tid - c * 5;
        const float bias = conv_b[c];
        const float* cw = conv_w + c * EMB * 3;
        for (int g = 0; g < 2; g++) {
            int wl = q * 8 + g * 4;
            float a0 = bias, a1 = bias, a2 = bias, a3 = bias;
#pragma unroll 4
            for (int e = 0; e < EMB; e++) {
                float c0 = cw[e * 3 + 0], c1 = cw[e * 3 + 1], c2 = cw[e * 3 + 2];
                float v0 = emb_s[wl + 0][e], v1 = emb_s[wl + 1][e], v2 = emb_s[wl + 2][e];
                float v3 = emb_s[wl + 3][e], v4 = emb_s[wl + 4][e], v5 = emb_s[wl + 5][e];
                a0 = fmaf(v0, c0, fmaf(v1, c1, fmaf(v2, c2, a0)));
                a1 = fmaf(v1, c0, fmaf(v2, c1, fmaf(v3, c2, a1)));
                a2 = fmaf(v2, c0, fmaf(v3, c1, fmaf(v4, c2, a2)));
                a3 = fmaf(v3, c0, fmaf(v4, c1, fmaf(v5, c2, a3)));
            }
            float* dst = g_H + ((long)b * CC + c) * WLEN + w0 + wl;
            dst[0] = tanhf(a0); dst[1] = tanhf(a1);
            dst[2] = tanhf(a2); dst[3] = tanhf(a3);
        }
    }
}

// ===========================================================================
// Kernel 2: dual GEMM via mma.sync tf32 (family-portable tensor path)
//   S = U . Hc^T, P = O . Hc^T, fused softmax-pool epilogue.
//   CTA: 128 labels x 64 w (8 warps, warp tile 32x32). K = 50 padded to 56.
//   No max-subtraction: |s| <= ~6 so exp() is safe in fp32.
// ===========================================================================
#define MT     128
#define NT     64
#define KP     56
#define USTR   136   // =8 mod 32 -> conflict-free fragment loads
#define HSTR   72    // =8 mod 32
#define NCHUNK 16    // 16*64 = 1024 >= 1000

#define SMEM_WORDS (2 * KP * USTR + KP * HSTR + 2 * MT)
#define SMEM_BYTES (SMEM_WORDS * 4)

#define MMA_TF32(C, A0, A1, A2, A3, B0, B1)                                 \
    asm volatile(                                                           \
        "mma.sync.aligned.m16n8k8.row.col.f32.tf32.tf32.f32 "               \
        "{%0,%1,%2,%3}, {%4,%5,%6,%7}, {%8,%9}, {%0,%1,%2,%3};"             \
        : "+f"((C)[0]), "+f"((C)[1]), "+f"((C)[2]), "+f"((C)[3])            \
        : "r"(A0), "r"(A1), "r"(A2), "r"(A3), "r"(B0), "r"(B1))

__device__ __forceinline__ uint32_t f2tf32(float v) {
    uint32_t t;
    asm("cvt.rna.tf32.f32 %0, %1;" : "=r"(t) : "f"(v));
    return t;
}

__global__ __launch_bounds__(256, 2)
void attn_kernel(const float* __restrict__ u_w, const float* __restrict__ out_w,
                 const float* __restrict__ out_b, float* __restrict__ out) {
    extern __shared__ uint32_t smw[];
    uint32_t* Us = smw;                       // [KP][USTR]
    uint32_t* Os = Us + KP * USTR;
    uint32_t* Hs = Os + KP * USTR;            // [KP][HSTR]
    float* pd = (float*)(Hs + KP * HSTR);     // [MT]
    float* pn = pd + MT;

    const int tid  = threadIdx.x;
    const int b    = blockIdx.y;
    const int l0   = blockIdx.x * MT;
    const int lane = tid & 31;
    const int wid  = tid >> 5;
    const int gid  = lane >> 2;   // 0..7
    const int tig  = lane & 3;    // 0..3
    const int wm   = wid & 3;     // label group
    const int wn   = wid >> 2;    // w group
    const int m0   = wm * 32;
    const int n0   = wn * 32;

    // Load U,O tiles (k-major, tf32-converted). Coalesced over k within label row.
    for (int i = tid; i < MT * KP; i += 256) {
        int k = i % KP;
        int m = i / KP;
        int l = l0 + m;
        float uv = 0.f, ov = 0.f;
        if (k < CC && l < LL) {
            uv = u_w[(long)l * CC + k];
            ov = out_w[(long)l * CC + k];
        }
        Us[k * USTR + m] = f2tf32(uv);
        Os[k * USTR + m] = f2tf32(ov);
    }

    float dstt[4] = {0.f, 0.f, 0.f, 0.f};   // softmax denominators (4 label rows/thread)
    float nstt[4] = {0.f, 0.f, 0.f, 0.f};   // weighted numerators

    for (int ch = 0; ch < NCHUNK; ch++) {
        const int wbase = ch * NT;
        __syncthreads();
        // Load H chunk [k][w], zero-padded; coalesced over w.
        for (int i = tid; i < KP * NT; i += 256) {
            int w = i & (NT - 1), k = i >> 6;
            int wg = wbase + w;
            float v = 0.f;
            if (k < CC && wg < WLEN) v = g_H[((long)b * CC + k) * WLEN + wg];
            Hs[k * HSTR + w] = f2tf32(v);
        }
        __syncthreads();

        float sacc[2][4][4], pacc[2][4][4];
#pragma unroll
        for (int mf = 0; mf < 2; mf++)
#pragma unroll
            for (int nf = 0; nf < 4; nf++)
#pragma unroll
                for (int c = 0; c < 4; c++) { sacc[mf][nf][c] = 0.f; pacc[mf][nf][c] = 0.f; }

#pragma unroll
        for (int ks = 0; ks < 7; ks++) {
            const int k0 = ks * 8;
            uint32_t bf0[4], bf1[4];
#pragma unroll
            for (int nf = 0; nf < 4; nf++) {
                bf0[nf] = Hs[(k0 + tig) * HSTR + n0 + nf * 8 + gid];
                bf1[nf] = Hs[(k0 + tig + 4) * HSTR + n0 + nf * 8 + gid];
            }
#pragma unroll
            for (int mf = 0; mf < 2; mf++) {
                const int mb = m0 + mf * 16 + gid;
                uint32_t a0 = Us[(k0 + tig) * USTR + mb];
                uint32_t a1 = Us[(k0 + tig) * USTR + mb + 8];
                uint32_t a2 = Us[(k0 + tig + 4) * USTR + mb];
                uint32_t a3 = Us[(k0 + tig + 4) * USTR + mb + 8];
#pragma unroll
                for (int nf = 0; nf < 4; nf++)
                    MMA_TF32(sacc[mf][nf], a0, a1, a2, a3, bf0[nf], bf1[nf]);
                a0 = Os[(k0 + tig) * USTR + mb];
                a1 = Os[(k0 + tig) * USTR + mb + 8];
                a2 = Os[(k0 + tig + 4) * USTR + mb];
                a3 = Os[(k0 + tig + 4) * USTR + mb + 8];
#pragma unroll
                for (int nf = 0; nf < 4; nf++)
                    MMA_TF32(pacc[mf][nf], a0, a1, a2, a3, bf0[nf], bf1[nf]);
            }
        }

        // Epilogue: e = exp(s) (w-masked), accumulate d and n per label row.
#pragma unroll
        for (int mf = 0; mf < 2; mf++)
#pragma unroll
            for (int nf = 0; nf < 4; nf++)
#pragma unroll
                for (int c = 0; c < 4; c++) {
                    int w = wbase + n0 + nf * 8 + 2 * tig + (c & 1);
                    float e = (w < WLEN) ? __expf(sacc[mf][nf][c]) : 0.f;
                    int idx = mf * 2 + (c >> 1);
                    dstt[idx] += e;
                    nstt[idx] = fmaf(e, pacc[mf][nf][c], nstt[idx]);
                }
    }

    // Reduce across the 4 k-group lanes (they hold different w columns).
#pragma unroll
    for (int idx = 0; idx < 4; idx++) {
        dstt[idx] += __shfl_xor_sync(0xffffffffu, dstt[idx], 1);
        dstt[idx] += __shfl_xor_sync(0xffffffffu, dstt[idx], 2);
        nstt[idx] += __shfl_xor_sync(0xffffffffu, nstt[idx], 1);
        nstt[idx] += __shfl_xor_sync(0xffffffffu, nstt[idx], 2);
    }

    // Merge the two w-warp-groups via smem, then finalize.
    __syncthreads();
    if (tig == 0 && wn == 1) {
#pragma unroll
        for (int idx = 0; idx < 4; idx++) {
            int row = m0 + (idx >> 1) * 16 + gid + (idx & 1) * 8;
            pd[row] = dstt[idx];
            pn[row] = nstt[idx];
        }
    }
    __syncthreads();
    if (tig == 0 && wn == 0) {
#pragma unroll
        for (int idx = 0; idx < 4; idx++) {
            int row = m0 + (idx >> 1) * 16 + gid + (idx & 1) * 8;
            int l = l0 + row;
            if (l < LL) {
                float dd = dstt[idx] + pd[row];
                float nn = nstt[idx] + pn[row];
                float z = nn / dd + out_b[l];
                out[(long)b * LL + l] = 1.f / (1.f + __expf(-z));
            }
        }
    }
}

// ===========================================================================
extern "C" void kernel_launch(void* const* d_in, const int* in_sizes, int n_in,
                              void* d_out, int out_size) {
    const int*   x       = (const int*)  d_in[0];
    const float* W_embed = (const float*)d_in[1];
    const float* conv_w  = (const float*)d_in[2];
    const float* conv_b  = (const float*)d_in[3];
    const float* u_w     = (const float*)d_in[4];
    const float* out_w   = (const float*)d_in[5];
    const float* out_b   = (const float*)d_in[6];
    float* out = (float*)d_out;

    cudaFuncSetAttribute(attn_kernel, cudaFuncAttributeMaxDynamicSharedMemorySize, SMEM_BYTES);

    dim3 cgrid(WLEN / CT_W, BB);          // (25, 8)
    conv_kernel<<<cgrid, 256>>>(x, W_embed, conv_w, conv_b);

    dim3 agrid((LL + MT - 1) / MT, BB);   // (141, 8)
    attn_kernel<<<agrid, 256, SMEM_BYTES>>>(u_w, out_w, out_b, out);
}

// round 4
// speedup vs baseline: 4.4074x; 1.4643x over previous
#include <cuda_runtime.h>
#include <cuda_fp16.h>
#include <math.h>
#include <stdint.h>

#define BB   8
#define WLEN 1000
#define EMB  100
#define CC   50
#define LL   18000

// H transposed scratch: [b][c][w] fp32
__device__ float g_H[BB * CC * WLEN];

// ===========================================================================
// Kernel 1: embedding + conv1d(k=3, same) + tanh  -> g_H[b][c][w]
// ===========================================================================
#define CT_W    40
#define CT_ROWS (CT_W + 2)

__global__ __launch_bounds__(256)
void conv_kernel(const int* __restrict__ x, const float* __restrict__ W_embed,
                 const float* __restrict__ conv_w, const float* __restrict__ conv_b) {
    __shared__ float emb_s[CT_ROWS][EMB + 1];
    __shared__ int   tok_s[CT_ROWS];
    const int b  = blockIdx.y;
    const int w0 = blockIdx.x * CT_W;
    const int tid = threadIdx.x;

    if (tid < CT_ROWS) {
        int w = w0 - 1 + tid;
        tok_s[tid] = (w >= 0 && w < WLEN) ? x[b * WLEN + w] : -1;
    }
    __syncthreads();
    for (int i = tid; i < CT_ROWS * EMB; i += 256) {
        int r = i / EMB, e = i - r * EMB;
        int t = tok_s[r];
        emb_s[r][e] = (t >= 0) ? W_embed[(long)t * EMB + e] : 0.f;
    }
    __syncthreads();

    if (tid < 250) {
        int c = tid / 5, q = tid - c * 5;
        const float bias = conv_b[c];
        const float* cw = conv_w + c * EMB * 3;
        for (int g = 0; g < 2; g++) {
            int wl = q * 8 + g * 4;
            float a0 = bias, a1 = bias, a2 = bias, a3 = bias;
#pragma unroll 4
            for (int e = 0; e < EMB; e++) {
                float c0 = cw[e * 3 + 0], c1 = cw[e * 3 + 1], c2 = cw[e * 3 + 2];
                float v0 = emb_s[wl + 0][e], v1 = emb_s[wl + 1][e], v2 = emb_s[wl + 2][e];
                float v3 = emb_s[wl + 3][e], v4 = emb_s[wl + 4][e], v5 = emb_s[wl + 5][e];
                a0 = fmaf(v0, c0, fmaf(v1, c1, fmaf(v2, c2, a0)));
                a1 = fmaf(v1, c0, fmaf(v2, c1, fmaf(v3, c2, a1)));
                a2 = fmaf(v2, c0, fmaf(v3, c1, fmaf(v4, c2, a2)));
                a3 = fmaf(v3, c0, fmaf(v4, c1, fmaf(v5, c2, a3)));
            }
            float* dst = g_H + ((long)b * CC + c) * WLEN + w0 + wl;
            dst[0] = tanhf(a0); dst[1] = tanhf(a1);
            dst[2] = tanhf(a2); dst[3] = tanhf(a3);
        }
    }
}

// ===========================================================================
// Kernel 2: dual GEMM via mma.sync fp16 m16n8k16 (fp32 accumulate)
//   S = U . Hc^T, P = O . Hc^T, fused softmax-pool epilogue (no max needed:
//   |s| <= ~6). Smem holds half2 k-pairs: [kp][m] / [kp][w].
//   CTA: 128 labels x 64 w (8 warps, warp tile 32x32). K = 50 padded to 64.
// ===========================================================================
#define MT     128
#define NT     64
#define KP2    32    // 64 k / 2 per half2
#define USTR   136   // =8 mod 32 -> conflict-free fragment loads
#define HSTR   72    // =8 mod 32
#define NCHUNK 16

#define SMEM_WORDS (2 * KP2 * USTR + KP2 * HSTR + 2 * MT)
#define SMEM_BYTES (SMEM_WORDS * 4)

#define MMA_F16(C, A0, A1, A2, A3, B0, B1)                                  \
    asm volatile(                                                           \
        "mma.sync.aligned.m16n8k16.row.col.f32.f16.f16.f32 "                \
        "{%0,%1,%2,%3}, {%4,%5,%6,%7}, {%8,%9}, {%0,%1,%2,%3};"             \
        : "+f"((C)[0]), "+f"((C)[1]), "+f"((C)[2]), "+f"((C)[3])            \
        : "r"(A0), "r"(A1), "r"(A2), "r"(A3), "r"(B0), "r"(B1))

__device__ __forceinline__ uint32_t packh2(float lo, float hi) {
    __half2 h = __floats2half2_rn(lo, hi);
    return *(uint32_t*)&h;
}

__global__ __launch_bounds__(256, 2)
void attn_kernel(const float* __restrict__ u_w, const float* __restrict__ out_w,
                 const float* __restrict__ out_b, float* __restrict__ out) {
    extern __shared__ uint32_t smw[];
    uint32_t* Us = smw;                       // [KP2][USTR]
    uint32_t* Os = Us + KP2 * USTR;
    uint32_t* Hs = Os + KP2 * USTR;           // [KP2][HSTR]
    float* pd = (float*)(Hs + KP2 * HSTR);    // [MT]
    float* pn = pd + MT;

    const int tid  = threadIdx.x;
    const int b    = blockIdx.y;
    const int l0   = blockIdx.x * MT;
    const int lane = tid & 31;
    const int wid  = tid >> 5;
    const int gid  = lane >> 2;   // 0..7
    const int tig  = lane & 3;    // 0..3
    const int wm   = wid & 3;     // label group
    const int wn   = wid >> 2;    // w group
    const int m0   = wm * 32;
    const int n0   = wn * 32;

    // Load U,O tiles as half2 k-pairs. Coalesced over kp within a label row.
    for (int i = tid; i < MT * KP2; i += 256) {
        int kp = i & (KP2 - 1);
        int m  = i >> 5;
        int l  = l0 + m;
        int k0 = 2 * kp, k1 = k0 + 1;
        float u0 = 0.f, u1 = 0.f, o0 = 0.f, o1 = 0.f;
        if (l < LL) {
            if (k0 < CC) { u0 = u_w[(long)l * CC + k0]; o0 = out_w[(long)l * CC + k0]; }
            if (k1 < CC) { u1 = u_w[(long)l * CC + k1]; o1 = out_w[(long)l * CC + k1]; }
        }
        Us[kp * USTR + m] = packh2(u0, u1);
        Os[kp * USTR + m] = packh2(o0, o1);
    }

    float dstt[4] = {0.f, 0.f, 0.f, 0.f};
    float nstt[4] = {0.f, 0.f, 0.f, 0.f};

    for (int ch = 0; ch < NCHUNK; ch++) {
        const int wbase = ch * NT;
        __syncthreads();
        // Load H chunk [kp][w] as half2 k-pairs; coalesced over w.
        for (int i = tid; i < KP2 * NT; i += 256) {
            int w  = i & (NT - 1), kp = i >> 6;
            int wg = wbase + w;
            int k0 = 2 * kp, k1 = k0 + 1;
            float v0 = 0.f, v1 = 0.f;
            if (wg < WLEN) {
                if (k0 < CC) v0 = g_H[((long)b * CC + k0) * WLEN + wg];
                if (k1 < CC) v1 = g_H[((long)b * CC + k1) * WLEN + wg];
            }
            Hs[kp * HSTR + w] = packh2(v0, v1);
        }
        __syncthreads();

        float sacc[2][4][4], pacc[2][4][4];
#pragma unroll
        for (int mf = 0; mf < 2; mf++)
#pragma unroll
            for (int nf = 0; nf < 4; nf++)
#pragma unroll
                for (int c = 0; c < 4; c++) { sacc[mf][nf][c] = 0.f; pacc[mf][nf][c] = 0.f; }

#pragma unroll
        for (int ks = 0; ks < 4; ks++) {            // 4 k-steps of 16
            const int kp0 = ks * 8;
            uint32_t bf0[4], bf1[4];
#pragma unroll
            for (int nf = 0; nf < 4; nf++) {
                bf0[nf] = Hs[(kp0 + tig) * HSTR + n0 + nf * 8 + gid];
                bf1[nf] = Hs[(kp0 + tig + 4) * HSTR + n0 + nf * 8 + gid];
            }
#pragma unroll
            for (int mf = 0; mf < 2; mf++) {
                const int mb = m0 + mf * 16 + gid;
                uint32_t a0 = Us[(kp0 + tig) * USTR + mb];
                uint32_t a1 = Us[(kp0 + tig) * USTR + mb + 8];
                uint32_t a2 = Us[(kp0 + tig + 4) * USTR + mb];
                uint32_t a3 = Us[(kp0 + tig + 4) * USTR + mb + 8];
#pragma unroll
                for (int nf = 0; nf < 4; nf++)
                    MMA_F16(sacc[mf][nf], a0, a1, a2, a3, bf0[nf], bf1[nf]);
                a0 = Os[(kp0 + tig) * USTR + mb];
                a1 = Os[(kp0 + tig) * USTR + mb + 8];
                a2 = Os[(kp0 + tig + 4) * USTR + mb];
                a3 = Os[(kp0 + tig + 4) * USTR + mb + 8];
#pragma unroll
                for (int nf = 0; nf < 4; nf++)
                    MMA_F16(pacc[mf][nf], a0, a1, a2, a3, bf0[nf], bf1[nf]);
            }
        }

        // Epilogue: e = exp(s) (w-masked), accumulate d and n per label row.
#pragma unroll
        for (int mf = 0; mf < 2; mf++)
#pragma unroll
            for (int nf = 0; nf < 4; nf++)
#pragma unroll
                for (int c = 0; c < 4; c++) {
                    int w = wbase + n0 + nf * 8 + 2 * tig + (c & 1);
                    float e = (w < WLEN) ? __expf(sacc[mf][nf][c]) : 0.f;
                    int idx = mf * 2 + (c >> 1);
                    dstt[idx] += e;
                    nstt[idx] = fmaf(e, pacc[mf][nf][c], nstt[idx]);
                }
    }

    // Reduce across the 4 k-group lanes (they hold different w columns).
#pragma unroll
    for (int idx = 0; idx < 4; idx++) {
        dstt[idx] += __shfl_xor_sync(0xffffffffu, dstt[idx], 1);
        dstt[idx] += __shfl_xor_sync(0xffffffffu, dstt[idx], 2);
        nstt[idx] += __shfl_xor_sync(0xffffffffu, nstt[idx], 1);
        nstt[idx] += __shfl_xor_sync(0xffffffffu, nstt[idx], 2);
    }

    // Merge the two w-warp-groups via smem, then finalize.
    __syncthreads();
    if (tig == 0 && wn == 1) {
#pragma unroll
        for (int idx = 0; idx < 4; idx++) {
            int row = m0 + (idx >> 1) * 16 + gid + (idx & 1) * 8;
            pd[row] = dstt[idx];
            pn[row] = nstt[idx];
        }
    }
    __syncthreads();
    if (tig == 0 && wn == 0) {
#pragma unroll
        for (int idx = 0; idx < 4; idx++) {
            int row = m0 + (idx >> 1) * 16 + gid + (idx & 1) * 8;
            int l = l0 + row;
            if (l < LL) {
                float dd = dstt[idx] + pd[row];
                float nn = nstt[idx] + pn[row];
                float z = nn / dd + out_b[l];
                out[(long)b * LL + l] = 1.f / (1.f + __expf(-z));
            }
        }
    }
}

// ===========================================================================
extern "C" void kernel_launch(void* const* d_in, const int* in_sizes, int n_in,
                              void* d_out, int out_size) {
    const int*   x       = (const int*)  d_in[0];
    const float* W_embed = (const float*)d_in[1];
    const float* conv_w  = (const float*)d_in[2];
    const float* conv_b  = (const float*)d_in[3];
    const float* u_w     = (const float*)d_in[4];
    const float* out_w   = (const float*)d_in[5];
    const float* out_b   = (const float*)d_in[6];
    float* out = (float*)d_out;

    cudaFuncSetAttribute(attn_kernel, cudaFuncAttributeMaxDynamicSharedMemorySize, SMEM_BYTES);

    dim3 cgrid(WLEN / CT_W, BB);          // (25, 8)
    conv_kernel<<<cgrid, 256>>>(x, W_embed, conv_w, conv_b);

    dim3 agrid((LL + MT - 1) / MT, BB);   // (141, 8)
    attn_kernel<<<agrid, 256, SMEM_BYTES>>>(u_w, out_w, out_b, out);
}

// round 5
// speedup vs baseline: 5.8227x; 1.3211x over previous
#include <cuda_runtime.h>
#include <cuda_fp16.h>
#include <math.h>
#include <stdint.h>

#define BB   8
#define WLEN 1000
#define EMB  100
#define CC   50
#define LL   18000

#define KPP  32      // padded k-pairs (k padded 50 -> 64)
#define WPAD 1024    // padded w

// zero-initialized device globals: padding (kp>=25, w>=1000) stays zero forever
__device__ uint32_t g_Hh[BB * KPP * WPAD];   // [b][kp][w] half2 (k-pair)
__device__ float    g_cwT[CC * 3 * EMB];     // [c][j][e]

// ===========================================================================
// Kernel 0: transpose conv_w [c][e][j] -> [c][j][e] (enables float4 e-loads)
// ===========================================================================
__global__ void prep_cw(const float* __restrict__ conv_w) {
    int i = blockIdx.x * 256 + threadIdx.x;
    if (i < CC * EMB * 3) {
        int c = i / (EMB * 3);
        int r = i - c * (EMB * 3);
        int e = r / 3, j = r - e * 3;
        g_cwT[(c * 3 + j) * EMB + e] = conv_w[i];
    }
}

// ===========================================================================
// Kernel 1: embedding + conv1d(k=3, same) + tanh -> packed half2 g_Hh[b][kp][w]
// thread = (channel pair, 4 w outputs); float4-vectorized over e
// ===========================================================================
#define CT_W    40
#define CT_ROWS (CT_W + 2)

__device__ __forceinline__ float dot4(float4 a, float4 b, float acc) {
    return fmaf(a.x, b.x, fmaf(a.y, b.y, fmaf(a.z, b.z, fmaf(a.w, b.w, acc))));
}

__global__ __launch_bounds__(256)
void conv_kernel(const int* __restrict__ x, const float* __restrict__ W_embed,
                 const float* __restrict__ conv_b) {
    __shared__ __align__(16) float emb_s[CT_ROWS][104];
    __shared__ int tok_s[CT_ROWS];
    const int b  = blockIdx.y;
    const int w0 = blockIdx.x * CT_W;
    const int tid = threadIdx.x;

    if (tid < CT_ROWS) {
        int w = w0 - 1 + tid;
        tok_s[tid] = (w >= 0 && w < WLEN) ? x[b * WLEN + w] : -1;
    }
    __syncthreads();
    for (int i = tid; i < CT_ROWS * 25; i += 256) {
        int r = i / 25, q = i - r * 25;
        int t = tok_s[r];
        float4 v = make_float4(0.f, 0.f, 0.f, 0.f);
        if (t >= 0) v = *(const float4*)&W_embed[(long)t * EMB + q * 4];
        *(float4*)&emb_s[r][q * 4] = v;
    }
    __syncthreads();

    if (tid < 250) {
        const int p = tid / 10, q = tid - p * 10;
        const int wl = q * 4;
        float acc[2][4];
        float b0 = conv_b[2 * p], b1 = conv_b[2 * p + 1];
#pragma unroll
        for (int w = 0; w < 4; w++) { acc[0][w] = b0; acc[1][w] = b1; }

        const float* cw0 = &g_cwT[(2 * p) * 3 * EMB];
        const float* cw1 = &g_cwT[(2 * p + 1) * 3 * EMB];

        for (int e4 = 0; e4 < 25; e4++) {
            float4 v[6];
#pragma unroll
            for (int r = 0; r < 6; r++) v[r] = *(const float4*)&emb_s[wl + r][e4 * 4];

            float4 c00 = *(const float4*)(cw0 + e4 * 4);
            float4 c01 = *(const float4*)(cw0 + EMB + e4 * 4);
            float4 c02 = *(const float4*)(cw0 + 2 * EMB + e4 * 4);
            float4 c10 = *(const float4*)(cw1 + e4 * 4);
            float4 c11 = *(const float4*)(cw1 + EMB + e4 * 4);
            float4 c12 = *(const float4*)(cw1 + 2 * EMB + e4 * 4);
#pragma unroll
            for (int w = 0; w < 4; w++) {
                acc[0][w] = dot4(v[w], c00, acc[0][w]);
                acc[0][w] = dot4(v[w + 1], c01, acc[0][w]);
                acc[0][w] = dot4(v[w + 2], c02, acc[0][w]);
                acc[1][w] = dot4(v[w], c10, acc[1][w]);
                acc[1][w] = dot4(v[w + 1], c11, acc[1][w]);
                acc[1][w] = dot4(v[w + 2], c12, acc[1][w]);
            }
        }
        uint4 ow;
        __half2 h0 = __floats2half2_rn(tanhf(acc[0][0]), tanhf(acc[1][0]));
        __half2 h1 = __floats2half2_rn(tanhf(acc[0][1]), tanhf(acc[1][1]));
        __half2 h2 = __floats2half2_rn(tanhf(acc[0][2]), tanhf(acc[1][2]));
        __half2 h3 = __floats2half2_rn(tanhf(acc[0][3]), tanhf(acc[1][3]));
        ow.x = *(uint32_t*)&h0; ow.y = *(uint32_t*)&h1;
        ow.z = *(uint32_t*)&h2; ow.w = *(uint32_t*)&h3;
        *(uint4*)&g_Hh[(b * KPP + p) * WPAD + w0 + wl] = ow;
    }
}

// ===========================================================================
// Kernel 2: dual GEMM, mma.sync fp16 m16n8k16, A fragments hoisted to regs.
//   8 warps x (m16 labels x n32 w). 32 chunks of 32 w, double-buffered smem.
//   U pre-scaled by log2(e) -> epilogue = ex2 + add + fma per element.
// ===========================================================================
#define NT   32
#define NCH  32
#define HSTR 40    // 40 % 32 == 8 -> conflict-free B-fragment LDS

#define MMA_F16(C, A0, A1, A2, A3, B0, B1)                                  \
    asm volatile(                                                           \
        "mma.sync.aligned.m16n8k16.row.col.f32.f16.f16.f32 "                \
        "{%0,%1,%2,%3}, {%4,%5,%6,%7}, {%8,%9}, {%0,%1,%2,%3};"             \
        : "+f"((C)[0]), "+f"((C)[1]), "+f"((C)[2]), "+f"((C)[3])            \
        : "r"(A0), "r"(A1), "r"(A2), "r"(A3), "r"(B0), "r"(B1))

__device__ __forceinline__ uint32_t packh2(float lo, float hi) {
    __half2 h = __floats2half2_rn(lo, hi);
    return *(uint32_t*)&h;
}

__global__ __launch_bounds__(256, 2)
void attn_kernel(const float* __restrict__ u_w, const float* __restrict__ out_w,
                 const float* __restrict__ out_b, float* __restrict__ out) {
    __shared__ uint32_t Hs[2][KPP * HSTR];

    const int tid  = threadIdx.x;
    const int b    = blockIdx.y;
    const int l0   = blockIdx.x * 128;
    const int lane = tid & 31;
    const int wid  = tid >> 5;
    const int gid  = lane >> 2;
    const int tig  = lane & 3;

    // ---- Hoisted A fragments (U scaled by log2 e; O plain), loaded from gmem
    const float LOG2E = 1.4426950408889634f;
    uint32_t uA[4][4], oA[4][4];
#pragma unroll
    for (int ks = 0; ks < 4; ks++)
#pragma unroll
        for (int h = 0; h < 2; h++) {
            int kp = ks * 8 + tig + h * 4;
#pragma unroll
            for (int mo = 0; mo < 2; mo++) {
                int l = l0 + wid * 16 + gid + mo * 8;
                float2 uv = make_float2(0.f, 0.f), ov = make_float2(0.f, 0.f);
                if (kp < 25 && l < LL) {
                    uv = *(const float2*)&u_w[l * CC + 2 * kp];
                    ov = *(const float2*)&out_w[l * CC + 2 * kp];
                }
                uA[ks][h * 2 + mo] = packh2(uv.x * LOG2E, uv.y * LOG2E);
                oA[ks][h * 2 + mo] = packh2(ov.x, ov.y);
            }
        }

    // ---- Prologue: load chunk 0
    const int kpr = tid >> 3;
    const int wq  = (tid & 7) * 4;
    {
        uint4 v = *(const uint4*)&g_Hh[(b * KPP + kpr) * WPAD + wq];
        *(uint4*)&Hs[0][kpr * HSTR + wq] = v;
    }
    __syncthreads();

    float dacc[2] = {0.f, 0.f}, nacc[2] = {0.f, 0.f};

    for (int ch = 0; ch < NCH; ch++) {
        const int cur = ch & 1;
        const bool more = (ch + 1 < NCH);
        uint4 nv = make_uint4(0, 0, 0, 0);
        if (more)
            nv = *(const uint4*)&g_Hh[(b * KPP + kpr) * WPAD + (ch + 1) * NT + wq];

        const uint32_t* Hb = Hs[cur];
        float sacc[4][4], pacc[4][4];
#pragma unroll
        for (int nf = 0; nf < 4; nf++)
#pragma unroll
            for (int c = 0; c < 4; c++) { sacc[nf][c] = 0.f; pacc[nf][c] = 0.f; }

#pragma unroll
        for (int ks = 0; ks < 4; ks++) {
            uint32_t bf0[4], bf1[4];
#pragma unroll
            for (int nf = 0; nf < 4; nf++) {
                bf0[nf] = Hb[(ks * 8 + tig) * HSTR + nf * 8 + gid];
                bf1[nf] = Hb[(ks * 8 + tig + 4) * HSTR + nf * 8 + gid];
            }
#pragma unroll
            for (int nf = 0; nf < 4; nf++) {
                MMA_F16(sacc[nf], uA[ks][0], uA[ks][1], uA[ks][2], uA[ks][3],
                        bf0[nf], bf1[nf]);
                MMA_F16(pacc[nf], oA[ks][0], oA[ks][1], oA[ks][2], oA[ks][3],
                        bf0[nf], bf1[nf]);
            }
        }

        // chunks 0..30 fully valid (31*32=992<1000); tail chunk: only nf==0 (w 992..999)
        const bool full = (ch < NCH - 1);
#pragma unroll
        for (int nf = 0; nf < 4; nf++) {
            if (full || nf == 0) {
#pragma unroll
                for (int c = 0; c < 4; c++) {
                    float e;
                    asm("ex2.approx.f32 %0, %1;" : "=f"(e) : "f"(sacc[nf][c]));
                    int r = c >> 1;
                    dacc[r] += e;
                    nacc[r] = fmaf(e, pacc[nf][c], nacc[r]);
                }
            }
        }

        if (more)
            *(uint4*)&Hs[1 - cur][kpr * HSTR + wq] = nv;
        __syncthreads();
    }

    // ---- Reduce over the 4 k-group lanes (different w columns), write out
#pragma unroll
    for (int r = 0; r < 2; r++) {
        dacc[r] += __shfl_xor_sync(0xffffffffu, dacc[r], 1);
        dacc[r] += __shfl_xor_sync(0xffffffffu, dacc[r], 2);
        nacc[r] += __shfl_xor_sync(0xffffffffu, nacc[r], 1);
        nacc[r] += __shfl_xor_sync(0xffffffffu, nacc[r], 2);
    }
    if (tig == 0) {
#pragma unroll
        for (int r = 0; r < 2; r++) {
            int l = l0 + wid * 16 + gid + r * 8;
            if (l < LL) {
                float z = nacc[r] / dacc[r] + out_b[l];
                out[b * LL + l] = 1.f / (1.f + __expf(-z));
            }
        }
    }
}

// ===========================================================================
extern "C" void kernel_launch(void* const* d_in, const int* in_sizes, int n_in,
                              void* d_out, int out_size) {
    const int*   x       = (const int*)  d_in[0];
    const float* W_embed = (const float*)d_in[1];
    const float* conv_w  = (const float*)d_in[2];
    const float* conv_b  = (const float*)d_in[3];
    const float* u_w     = (const float*)d_in[4];
    const float* out_w   = (const float*)d_in[5];
    const float* out_b   = (const float*)d_in[6];
    float* out = (float*)d_out;

    prep_cw<<<(CC * EMB * 3 + 255) / 256, 256>>>(conv_w);

    dim3 cgrid(WLEN / CT_W, BB);          // (25, 8)
    conv_kernel<<<cgrid, 256>>>(x, W_embed, conv_b);

    dim3 agrid((LL + 127) / 128, BB);     // (141, 8)
    attn_kernel<<<agrid, 256>>>(u_w, out_w, out_b, out);
}